// round 1
// baseline (speedup 1.0000x reference)
#include <cuda_runtime.h>
#include <cuda_bf16.h>
#include <cstdint>
#include <cstddef>

#define FD 128
#define NN 25000
#define NE 400000
// smem: A_hi, A_lo, B_hi, B_lo each 128 x 136 bf16
#define SMEM_BYTES (4 * 128 * 136 * 2)

// ---------------- scratch (device globals; no allocation allowed) ----------
__device__ float g_P[NN * FD];
__device__ float g_Q[NN * FD];
__device__ float g_eps[NN];
__device__ float g_a[NE];
__device__ __nv_bfloat16 g_W[4][2][FD * FD];  // [Wt,Wm,Wb,We1][hi/lo][n*FD+k] (col-of-W contiguous in k)
__device__ int g_deg[NN];
__device__ int g_off[NN + 1];
__device__ int g_cur[NN];
__device__ int g_eid[NE];

// ---------------- weight split + transpose + zero histogram ----------------
__global__ void k_prep(const float* __restrict__ Wa1, const float* __restrict__ We1) {
    int stride = gridDim.x * blockDim.x;
    int tid = blockIdx.x * blockDim.x + threadIdx.x;
    for (int i = tid; i < 4 * FD * FD; i += stride) {
        int m = i >> 14;
        int r = i & (FD * FD - 1);
        int n = r >> 7;
        int k = r & 127;
        float w = (m < 3) ? Wa1[(m * FD + k) * FD + n] : We1[k * FD + n];
        __nv_bfloat16 hi = __float2bfloat16(w);
        float lo = w - __bfloat162float(hi);
        g_W[m][0][n * FD + k] = hi;
        g_W[m][1][n * FD + k] = __float2bfloat16(lo);
    }
    for (int i = tid; i < NN; i += stride) g_deg[i] = 0;
}

// ---------------- mma helpers ----------------------------------------------
__device__ __forceinline__ uint32_t lds32(const __nv_bfloat16* base, int row, int col) {
    return *reinterpret_cast<const uint32_t*>(base + row * 136 + col);
}

__device__ __forceinline__ void mma_bf16(float c[4], uint32_t a0, uint32_t a1, uint32_t a2,
                                         uint32_t a3, uint32_t b0, uint32_t b1) {
    asm volatile(
        "mma.sync.aligned.m16n8k16.row.col.f32.bf16.bf16.f32 "
        "{%0,%1,%2,%3},{%4,%5,%6,%7},{%8,%9},{%0,%1,%2,%3};"
        : "+f"(c[0]), "+f"(c[1]), "+f"(c[2]), "+f"(c[3])
        : "r"(a0), "r"(a1), "r"(a2), "r"(a3), "r"(b0), "r"(b1));
}

// C tile 128x128 per block; warp grid 4(M) x 2(N); warp tile 32x64.
__device__ __forceinline__ void run_mainloop(const __nv_bfloat16* sA_hi,
                                             const __nv_bfloat16* sA_lo,
                                             const __nv_bfloat16* sB_hi,
                                             const __nv_bfloat16* sB_lo,
                                             float C[2][8][4]) {
    int lane = threadIdx.x & 31;
    int wid = threadIdx.x >> 5;
    int wm = wid >> 1, wn = wid & 1;
    int g = lane >> 2, q = lane & 3;
#pragma unroll
    for (int ks = 0; ks < 8; ks++) {
        int k0 = ks * 16 + q * 2;
        uint32_t Ah[2][4], Al[2][4];
#pragma unroll
        for (int mt = 0; mt < 2; mt++) {
            int r = wm * 32 + mt * 16 + g;
            Ah[mt][0] = lds32(sA_hi, r, k0);
            Ah[mt][1] = lds32(sA_hi, r + 8, k0);
            Ah[mt][2] = lds32(sA_hi, r, k0 + 8);
            Ah[mt][3] = lds32(sA_hi, r + 8, k0 + 8);
            Al[mt][0] = lds32(sA_lo, r, k0);
            Al[mt][1] = lds32(sA_lo, r + 8, k0);
            Al[mt][2] = lds32(sA_lo, r, k0 + 8);
            Al[mt][3] = lds32(sA_lo, r + 8, k0 + 8);
        }
#pragma unroll
        for (int nt = 0; nt < 8; nt++) {
            int n = wn * 64 + nt * 8 + g;
            uint32_t bh0 = lds32(sB_hi, n, k0);
            uint32_t bh1 = lds32(sB_hi, n, k0 + 8);
            uint32_t bl0 = lds32(sB_lo, n, k0);
            uint32_t bl1 = lds32(sB_lo, n, k0 + 8);
#pragma unroll
            for (int mt = 0; mt < 2; mt++) {
                mma_bf16(C[mt][nt], Ah[mt][0], Ah[mt][1], Ah[mt][2], Ah[mt][3], bh0, bh1);
                mma_bf16(C[mt][nt], Al[mt][0], Al[mt][1], Al[mt][2], Al[mt][3], bh0, bh1);
                mma_bf16(C[mt][nt], Ah[mt][0], Ah[mt][1], Ah[mt][2], Ah[mt][3], bl0, bl1);
            }
        }
    }
}

__device__ __forceinline__ void load_A_tile(const float* __restrict__ src, int row0, int maxrow,
                                            __nv_bfloat16* sA_hi, __nv_bfloat16* sA_lo) {
    int tid = threadIdx.x;
#pragma unroll
    for (int it = 0; it < 16; it++) {
        int linear = it * 256 + tid;
        int r = linear >> 5;
        int c = (linear & 31) * 4;
        float4 v = make_float4(0.f, 0.f, 0.f, 0.f);
        if (row0 + r < maxrow)
            v = *reinterpret_cast<const float4*>(src + (size_t)(row0 + r) * FD + c);
        __nv_bfloat16 h0 = __float2bfloat16(v.x);
        __nv_bfloat16 h1 = __float2bfloat16(v.y);
        __nv_bfloat16 h2 = __float2bfloat16(v.z);
        __nv_bfloat16 h3 = __float2bfloat16(v.w);
        __nv_bfloat16 l0 = __float2bfloat16(v.x - __bfloat162float(h0));
        __nv_bfloat16 l1 = __float2bfloat16(v.y - __bfloat162float(h1));
        __nv_bfloat16 l2 = __float2bfloat16(v.z - __bfloat162float(h2));
        __nv_bfloat16 l3 = __float2bfloat16(v.w - __bfloat162float(h3));
        __nv_bfloat16* ph = sA_hi + r * 136 + c;
        __nv_bfloat16* pl = sA_lo + r * 136 + c;
        __nv_bfloat162 t;
        t.x = h0; t.y = h1; *reinterpret_cast<__nv_bfloat162*>(ph) = t;
        t.x = h2; t.y = h3; *reinterpret_cast<__nv_bfloat162*>(ph + 2) = t;
        t.x = l0; t.y = l1; *reinterpret_cast<__nv_bfloat162*>(pl) = t;
        t.x = l2; t.y = l3; *reinterpret_cast<__nv_bfloat162*>(pl + 2) = t;
    }
}

__device__ __forceinline__ void load_B_tile(const __nv_bfloat16* __restrict__ hi_src,
                                            const __nv_bfloat16* __restrict__ lo_src,
                                            __nv_bfloat16* sB_hi, __nv_bfloat16* sB_lo) {
    int tid = threadIdx.x;
    const uint32_t* sh = reinterpret_cast<const uint32_t*>(hi_src);
    const uint32_t* sl = reinterpret_cast<const uint32_t*>(lo_src);
#pragma unroll
    for (int it = 0; it < 32; it++) {
        int linear = it * 256 + tid;  // 8192 uint32 per matrix
        int n = linear >> 6;
        int kk = linear & 63;
        *reinterpret_cast<uint32_t*>(sB_hi + n * 136 + kk * 2) = sh[linear];
        *reinterpret_cast<uint32_t*>(sB_lo + n * 136 + kk * 2) = sl[linear];
    }
}

__device__ __forceinline__ void stage_C(float C[2][8][4], float* Gst) {
    int lane = threadIdx.x & 31;
    int wid = threadIdx.x >> 5;
    int wm = wid >> 1, wn = wid & 1, g = lane >> 2, q = lane & 3;
#pragma unroll
    for (int mt = 0; mt < 2; mt++)
#pragma unroll
        for (int nt = 0; nt < 8; nt++) {
            int row = wm * 32 + mt * 16 + g;
            int col = wn * 64 + nt * 8 + q * 2;
            float2 v0 = make_float2(C[mt][nt][0], C[mt][nt][1]);
            float2 v1 = make_float2(C[mt][nt][2], C[mt][nt][3]);
            *reinterpret_cast<float2*>(Gst + row * 132 + col) = v0;
            *reinterpret_cast<float2*>(Gst + (row + 8) * 132 + col) = v1;
        }
}

// ---------------- node kernel: P, Q, eps -----------------------------------
__global__ void __launch_bounds__(256, 1)
k_node(const float* __restrict__ nf, const float* __restrict__ be1,
       const float* __restrict__ We2, const float* __restrict__ be2) {
    extern __shared__ char smem[];
    __nv_bfloat16* sA_hi = reinterpret_cast<__nv_bfloat16*>(smem);
    __nv_bfloat16* sA_lo = sA_hi + 128 * 136;
    __nv_bfloat16* sB_hi = sA_lo + 128 * 136;
    __nv_bfloat16* sB_lo = sB_hi + 128 * 136;
    float* Gst = reinterpret_cast<float*>(smem);

    int m0 = blockIdx.x * 128;
    load_A_tile(nf, m0, NN, sA_hi, sA_lo);

    int lane = threadIdx.x & 31;
    int wid = threadIdx.x >> 5;
    int wm = wid >> 1, wn = wid & 1, g = lane >> 2, q = lane & 3;

    // P (Wt) then Q (Wm): direct global stores
    for (int wsel = 0; wsel < 2; wsel++) {
        __syncthreads();
        load_B_tile(g_W[wsel][0], g_W[wsel][1], sB_hi, sB_lo);
        __syncthreads();
        float C[2][8][4];
#pragma unroll
        for (int a = 0; a < 2; a++)
#pragma unroll
            for (int b = 0; b < 8; b++)
#pragma unroll
                for (int cc = 0; cc < 4; cc++) C[a][b][cc] = 0.f;
        run_mainloop(sA_hi, sA_lo, sB_hi, sB_lo, C);
        float* dstbuf = (wsel == 0) ? g_P : g_Q;
#pragma unroll
        for (int mt = 0; mt < 2; mt++)
#pragma unroll
            for (int nt = 0; nt < 8; nt++) {
                int row = m0 + wm * 32 + mt * 16 + g;
                int col = wn * 64 + nt * 8 + q * 2;
                if (row < NN) {
                    float2 v = make_float2(C[mt][nt][0], C[mt][nt][1]);
                    *reinterpret_cast<float2*>(dstbuf + (size_t)row * FD + col) = v;
                }
                if (row + 8 < NN) {
                    float2 v = make_float2(C[mt][nt][2], C[mt][nt][3]);
                    *reinterpret_cast<float2*>(dstbuf + (size_t)(row + 8) * FD + col) = v;
                }
            }
    }

    // eps = relu(nf@We1 + be1) . We2 + be2
    __syncthreads();
    load_B_tile(g_W[3][0], g_W[3][1], sB_hi, sB_lo);
    __syncthreads();
    float C[2][8][4];
#pragma unroll
    for (int a = 0; a < 2; a++)
#pragma unroll
        for (int b = 0; b < 8; b++)
#pragma unroll
            for (int cc = 0; cc < 4; cc++) C[a][b][cc] = 0.f;
    run_mainloop(sA_hi, sA_lo, sB_hi, sB_lo, C);
    __syncthreads();  // done reading sA; about to clobber with Gst
    stage_C(C, Gst);
    __syncthreads();

    float4 bv = *reinterpret_cast<const float4*>(be1 + lane * 4);
    float4 w2 = *reinterpret_cast<const float4*>(We2 + lane * 4);
    float b2 = be2[0];
    for (int rr = 0; rr < 16; rr++) {
        int r = wid * 16 + rr;
        int node = m0 + r;
        float4 h = *reinterpret_cast<const float4*>(Gst + r * 132 + lane * 4);
        float p = fmaxf(h.x + bv.x, 0.f) * w2.x + fmaxf(h.y + bv.y, 0.f) * w2.y +
                  fmaxf(h.z + bv.z, 0.f) * w2.z + fmaxf(h.w + bv.w, 0.f) * w2.w;
#pragma unroll
        for (int d = 16; d; d >>= 1) p += __shfl_xor_sync(0xffffffffu, p, d);
        if (lane == 0 && node < NN) g_eps[node] = p + b2;
    }
}

// ---------------- edge kernel: a[e] ----------------------------------------
__global__ void __launch_bounds__(256, 1)
k_edge(const float* __restrict__ gh, const int* __restrict__ src, const int* __restrict__ dst,
       const float* __restrict__ ba1, const float* __restrict__ Wa2,
       const float* __restrict__ ba2) {
    extern __shared__ char smem[];
    __nv_bfloat16* sA_hi = reinterpret_cast<__nv_bfloat16*>(smem);
    __nv_bfloat16* sA_lo = sA_hi + 128 * 136;
    __nv_bfloat16* sB_hi = sA_lo + 128 * 136;
    __nv_bfloat16* sB_lo = sB_hi + 128 * 136;
    float* Gst = reinterpret_cast<float*>(smem);

    int m0 = blockIdx.x * 128;
    load_A_tile(gh, m0, NE, sA_hi, sA_lo);
    load_B_tile(g_W[2][0], g_W[2][1], sB_hi, sB_lo);
    __syncthreads();

    float C[2][8][4];
#pragma unroll
    for (int a = 0; a < 2; a++)
#pragma unroll
        for (int b = 0; b < 8; b++)
#pragma unroll
            for (int cc = 0; cc < 4; cc++) C[a][b][cc] = 0.f;
    run_mainloop(sA_hi, sA_lo, sB_hi, sB_lo, C);
    __syncthreads();
    stage_C(C, Gst);
    __syncthreads();

    int lane = threadIdx.x & 31;
    int wid = threadIdx.x >> 5;
    float4 bv = *reinterpret_cast<const float4*>(ba1 + lane * 4);
    float4 w2 = *reinterpret_cast<const float4*>(Wa2 + lane * 4);
    float b2 = ba2[0];
    for (int rr = 0; rr < 16; rr++) {
        int r = wid * 16 + rr;
        int e = m0 + r;
        int es = src[e];
        int ed = dst[e];
        float4 gv = *reinterpret_cast<const float4*>(Gst + r * 132 + lane * 4);
        float4 pv = *reinterpret_cast<const float4*>(g_P + (size_t)es * FD + lane * 4);
        float4 qv = *reinterpret_cast<const float4*>(g_Q + (size_t)ed * FD + lane * 4);
        float p = fmaxf(gv.x + pv.x + qv.x + bv.x, 0.f) * w2.x +
                  fmaxf(gv.y + pv.y + qv.y + bv.y, 0.f) * w2.y +
                  fmaxf(gv.z + pv.z + qv.z + bv.z, 0.f) * w2.z +
                  fmaxf(gv.w + pv.w + qv.w + bv.w, 0.f) * w2.w;
#pragma unroll
        for (int d = 16; d; d >>= 1) p += __shfl_xor_sync(0xffffffffu, p, d);
        if (lane == 0) g_a[e] = p + b2;
    }
}

// ---------------- CSR build -------------------------------------------------
__global__ void k_hist(const int* __restrict__ dst) {
    int e = blockIdx.x * blockDim.x + threadIdx.x;
    if (e < NE) atomicAdd(&g_deg[dst[e]], 1);
}

__global__ void k_scan() {
    __shared__ int wsum[32];
    int tid = threadIdx.x;
    int lane = tid & 31, w = tid >> 5;
    int carry = 0;
    for (int c = 0; c < (NN + 1024) / 1024; c++) {
        int idx = c * 1024 + tid;
        int v = (idx < NN) ? g_deg[idx] : 0;
        int x = v;
#pragma unroll
        for (int d = 1; d < 32; d <<= 1) {
            int t = __shfl_up_sync(0xffffffffu, x, d);
            if (lane >= d) x += t;
        }
        if (lane == 31) wsum[w] = x;
        __syncthreads();
        if (w == 0) {
            int y = wsum[lane];
#pragma unroll
            for (int d = 1; d < 32; d <<= 1) {
                int t = __shfl_up_sync(0xffffffffu, y, d);
                if (lane >= d) y += t;
            }
            wsum[lane] = y;
        }
        __syncthreads();
        int woff = (w > 0) ? wsum[w - 1] : 0;
        int excl = carry + woff + x - v;
        if (idx <= NN) {
            g_off[idx] = excl;
            if (idx < NN) g_cur[idx] = excl;
        }
        carry += wsum[31];
        __syncthreads();
    }
}

__global__ void k_scatter(const int* __restrict__ dst) {
    int e = blockIdx.x * blockDim.x + threadIdx.x;
    if (e < NE) {
        int p = atomicAdd(&g_cur[dst[e]], 1);
        g_eid[p] = e;
    }
}

// ---------------- aggregation: online softmax, warp per node ---------------
__global__ void k_agg(const float* __restrict__ nf, const float* __restrict__ gh,
                      const int* __restrict__ src, float* __restrict__ out) {
    int warp = (blockIdx.x * blockDim.x + threadIdx.x) >> 5;
    int lane = threadIdx.x & 31;
    if (warp >= NN) return;
    int beg = g_off[warp];
    int end = g_off[warp + 1];
    float m = -INFINITY, s = 0.f;
    float4 hv = make_float4(0.f, 0.f, 0.f, 0.f);
    const float4* nf4 = reinterpret_cast<const float4*>(nf);
    for (int i = beg; i < end; i++) {
        int e = g_eid[i];
        float av = g_a[e];
        int es = src[e];
        float mn = fmaxf(m, av);
        float c1 = __expf(m - mn);
        float w = __expf(av - mn);
        s = s * c1 + w;
        float4 gv = *reinterpret_cast<const float4*>(gh + (size_t)e * FD + lane * 4);
        float4 h = nf4[(size_t)es * 32 + lane];
        hv.x = hv.x * c1 + w * gv.x * h.x;
        hv.y = hv.y * c1 + w * gv.y * h.y;
        hv.z = hv.z * c1 + w * gv.z * h.z;
        hv.w = hv.w * c1 + w * gv.w * h.w;
        m = mn;
    }
    float inv = (s > 0.f) ? 1.f / s : 0.f;
    float ep = 1.f + g_eps[warp];
    float4 base = nf4[(size_t)warp * 32 + lane];
    float4 r;
    r.x = ep * hv.x * inv + base.x;
    r.y = ep * hv.y * inv + base.y;
    r.z = ep * hv.z * inv + base.z;
    r.w = ep * hv.w * inv + base.w;
    reinterpret_cast<float4*>(out)[(size_t)warp * 32 + lane] = r;
}

// ---------------- launch ----------------------------------------------------
extern "C" void kernel_launch(void* const* d_in, const int* in_sizes, int n_in,
                              void* d_out, int out_size) {
    const float* nf = (const float*)d_in[0];
    const float* gh = (const float*)d_in[1];
    const int* src = (const int*)d_in[2];
    const int* dst = (const int*)d_in[3];
    const float* Wa1 = (const float*)d_in[4];
    const float* ba1 = (const float*)d_in[5];
    const float* Wa2 = (const float*)d_in[6];
    const float* ba2 = (const float*)d_in[7];
    const float* We1 = (const float*)d_in[8];
    const float* be1 = (const float*)d_in[9];
    const float* We2 = (const float*)d_in[10];
    const float* be2 = (const float*)d_in[11];
    float* out = (float*)d_out;

    cudaFuncSetAttribute(k_node, cudaFuncAttributeMaxDynamicSharedMemorySize, SMEM_BYTES);
    cudaFuncSetAttribute(k_edge, cudaFuncAttributeMaxDynamicSharedMemorySize, SMEM_BYTES);

    k_prep<<<128, 256>>>(Wa1, We1);
    k_node<<<(NN + 127) / 128, 256, SMEM_BYTES>>>(nf, be1, We2, be2);
    k_edge<<<NE / 128, 256, SMEM_BYTES>>>(gh, src, dst, ba1, Wa2, ba2);
    k_hist<<<(NE + 255) / 256, 256>>>(dst);
    k_scan<<<1, 1024>>>();
    k_scatter<<<(NE + 255) / 256, 256>>>(dst);
    k_agg<<<(NN * 32 + 255) / 256, 256>>>(nf, gh, src, out);
}

// round 3
// speedup vs baseline: 1.4168x; 1.4168x over previous
#include <cuda_runtime.h>
#include <cuda_fp16.h>
#include <cstdint>
#include <cstddef>

#define FD 128
#define NN 25000
#define NE 400000
#define TILE 128
// smem: A 128x136 fp16 (34816 B) + B 128x136 fp16 (34816 B); staging Gst 128x132 f32 overlaps
#define SMEM_BYTES (2 * 128 * 136 * 2)

// ---------------- device scratch (no allocation allowed) --------------------
__device__ float g_P[NN * FD];
__device__ float g_Q[NN * FD];
__device__ float g_eps[NN];
__device__ float g_a[NE];
__device__ __half g_W[4][FD * FD];  // [Wt,Wm,Wb,We1] stored [n*FD+k]
__device__ int g_deg[NN];
__device__ int g_off[NN + 1];
__device__ int g_cur[NN];
__device__ int g_eid[NE];

// ---------------- helpers ----------------------------------------------------
__device__ __forceinline__ uint32_t smem_u32(const void* p) {
    uint32_t a;
    asm("{ .reg .u64 t; cvta.to.shared.u64 t, %1; cvt.u32.u64 %0, t; }" : "=r"(a) : "l"(p));
    return a;
}
__device__ __forceinline__ void ldsm4(uint32_t r[4], uint32_t addr) {
    asm volatile("ldmatrix.sync.aligned.m8n8.x4.shared.b16 {%0,%1,%2,%3}, [%4];"
                 : "=r"(r[0]), "=r"(r[1]), "=r"(r[2]), "=r"(r[3])
                 : "r"(addr));
}
__device__ __forceinline__ void mma16816(float c[4], const uint32_t a[4], uint32_t b0,
                                         uint32_t b1) {
    asm volatile(
        "mma.sync.aligned.m16n8k16.row.col.f32.f16.f16.f32 "
        "{%0,%1,%2,%3},{%4,%5,%6,%7},{%8,%9},{%0,%1,%2,%3};"
        : "+f"(c[0]), "+f"(c[1]), "+f"(c[2]), "+f"(c[3])
        : "r"(a[0]), "r"(a[1]), "r"(a[2]), "r"(a[3]), "r"(b0), "r"(b1));
}
__device__ __forceinline__ uint32_t pack_h2(float x, float y) {
    __half2 h = __floats2half2_rn(x, y);
    return *reinterpret_cast<uint32_t*>(&h);
}

// ---------------- weight convert + zero histogram ---------------------------
__global__ void k_prep(const float* __restrict__ Wa1, const float* __restrict__ We1) {
    int stride = gridDim.x * blockDim.x;
    int tid = blockIdx.x * blockDim.x + threadIdx.x;
    for (int i = tid; i < 4 * FD * FD; i += stride) {
        int m = i >> 14;
        int r = i & (FD * FD - 1);
        int n = r >> 7;
        int k = r & 127;
        float w = (m < 3) ? Wa1[(m * FD + k) * FD + n] : We1[k * FD + n];
        g_W[m][n * FD + k] = __float2half(w);
    }
    for (int i = tid; i < NN; i += stride) g_deg[i] = 0;
}

// ---------------- GEMM building blocks (256 threads, C tile 128x128) --------
// A in smem[0..34816), row stride 272B; B in smem[34816..69632)
__device__ __forceinline__ void load_A(const float* __restrict__ src, int row0, int maxrow,
                                       char* smem) {
    int t = threadIdx.x;
#pragma unroll
    for (int it = 0; it < 16; it++) {
        int linear = it * 256 + t;
        int r = linear >> 5;
        int c = (linear & 31) * 4;  // float col
        float4 v = make_float4(0.f, 0.f, 0.f, 0.f);
        if (row0 + r < maxrow)
            v = *reinterpret_cast<const float4*>(src + (size_t)(row0 + r) * FD + c);
        uint2 pk;
        pk.x = pack_h2(v.x, v.y);
        pk.y = pack_h2(v.z, v.w);
        *reinterpret_cast<uint2*>(smem + r * 272 + c * 2) = pk;
    }
}
__device__ __forceinline__ void load_B(const __half* __restrict__ w, char* smem) {
    const uint32_t* s4 = reinterpret_cast<const uint32_t*>(w);
    int t = threadIdx.x;
    char* sB = smem + 34816;
#pragma unroll
    for (int it = 0; it < 32; it++) {
        int linear = it * 256 + t;  // 8192 half2
        int n = linear >> 6;
        int kk = linear & 63;
        *reinterpret_cast<uint32_t*>(sB + n * 272 + kk * 4) = s4[linear];
    }
}

// warp grid 4(M) x 2(N); warp tile 32x64; per-thread C[2][8][4]
__device__ __forceinline__ void mainloop(char* smem, float C[2][8][4]) {
    int lane = threadIdx.x & 31;
    int wid = threadIdx.x >> 5;
    int wm = wid >> 1, wn = wid & 1;
    uint32_t sA = smem_u32(smem);
    uint32_t sB = sA + 34816;
    uint32_t aA0 = sA + (wm * 32 + (lane & 15)) * 272 + (lane >> 4) * 16;
    uint32_t aA1 = aA0 + 16 * 272;
    uint32_t aB[4];
#pragma unroll
    for (int p = 0; p < 4; p++)
        aB[p] = sB + (wn * 64 + p * 16 + (lane & 7) + ((lane >> 4) & 1) * 8) * 272 +
                ((lane >> 3) & 1) * 16;
#pragma unroll
    for (int ks = 0; ks < 8; ks++) {
        uint32_t A0[4], A1[4], Bf[4][4];
        ldsm4(A0, aA0 + ks * 32);
        ldsm4(A1, aA1 + ks * 32);
#pragma unroll
        for (int p = 0; p < 4; p++) ldsm4(Bf[p], aB[p] + ks * 32);
#pragma unroll
        for (int p = 0; p < 4; p++) {
            mma16816(C[0][2 * p], A0, Bf[p][0], Bf[p][1]);
            mma16816(C[1][2 * p], A1, Bf[p][0], Bf[p][1]);
            mma16816(C[0][2 * p + 1], A0, Bf[p][2], Bf[p][3]);
            mma16816(C[1][2 * p + 1], A1, Bf[p][2], Bf[p][3]);
        }
    }
}

__device__ __forceinline__ void zero_C(float C[2][8][4]) {
#pragma unroll
    for (int a = 0; a < 2; a++)
#pragma unroll
        for (int b = 0; b < 8; b++)
#pragma unroll
            for (int c = 0; c < 4; c++) C[a][b][c] = 0.f;
}

__device__ __forceinline__ void stage_C(float C[2][8][4], float* Gst) {
    int lane = threadIdx.x & 31;
    int wid = threadIdx.x >> 5;
    int wm = wid >> 1, wn = wid & 1, g = lane >> 2, q = lane & 3;
#pragma unroll
    for (int mt = 0; mt < 2; mt++)
#pragma unroll
        for (int nt = 0; nt < 8; nt++) {
            int row = wm * 32 + mt * 16 + g;
            int col = wn * 64 + nt * 8 + q * 2;
            *reinterpret_cast<float2*>(Gst + row * 132 + col) = make_float2(C[mt][nt][0], C[mt][nt][1]);
            *reinterpret_cast<float2*>(Gst + (row + 8) * 132 + col) = make_float2(C[mt][nt][2], C[mt][nt][3]);
        }
}

// ---------------- edge kernel: a[e] = relu(G+P[src]+Q[dst]+ba1).Wa2 + ba2 ---
__global__ void __launch_bounds__(256, 2)
k_edge(const float* __restrict__ gh, const int* __restrict__ src, const int* __restrict__ dst,
       const float* __restrict__ ba1, const float* __restrict__ Wa2, const float* __restrict__ ba2) {
    extern __shared__ char smem[];
    int m0 = blockIdx.x * TILE;
    load_A(gh, m0, NE, smem);
    load_B(g_W[2], smem);
    __syncthreads();

    float C[2][8][4];
    zero_C(C);
    mainloop(smem, C);
    __syncthreads();
    float* Gst = reinterpret_cast<float*>(smem);
    stage_C(C, Gst);
    __syncthreads();

    int lane = threadIdx.x & 31;
    int wid = threadIdx.x >> 5;
    int half = lane >> 4;
    int r = wid * 16 + (lane & 15);
    int e = m0 + r;
    int es = src[e], ed = dst[e];
    if (half == 0) atomicAdd(&g_deg[ed], 1);
    float acc = 0.f;
    const float4* Gp = reinterpret_cast<const float4*>(Gst + r * 132 + half * 64);
    const float4* Pp = reinterpret_cast<const float4*>(g_P + (size_t)es * FD + half * 64);
    const float4* Qp = reinterpret_cast<const float4*>(g_Q + (size_t)ed * FD + half * 64);
    const float4* Bp = reinterpret_cast<const float4*>(ba1 + half * 64);
    const float4* Wp = reinterpret_cast<const float4*>(Wa2 + half * 64);
#pragma unroll
    for (int j = 0; j < 16; j++) {
        float4 gv = Gp[j], pv = Pp[j], qv = Qp[j], bv = Bp[j], wv = Wp[j];
        acc += fmaxf(gv.x + pv.x + qv.x + bv.x, 0.f) * wv.x;
        acc += fmaxf(gv.y + pv.y + qv.y + bv.y, 0.f) * wv.y;
        acc += fmaxf(gv.z + pv.z + qv.z + bv.z, 0.f) * wv.z;
        acc += fmaxf(gv.w + pv.w + qv.w + bv.w, 0.f) * wv.w;
    }
    acc += __shfl_xor_sync(0xffffffffu, acc, 16);
    if (half == 0) g_a[e] = acc + ba2[0];
}

// ---------------- node kernel: P = nf@Wt, Q = nf@Wm, eps --------------------
__global__ void __launch_bounds__(256, 2)
k_node(const float* __restrict__ nf, const float* __restrict__ be1, const float* __restrict__ We2,
       const float* __restrict__ be2) {
    extern __shared__ char smem[];
    int m0 = blockIdx.x * TILE;
    load_A(nf, m0, NN, smem);

    int lane = threadIdx.x & 31;
    int wid = threadIdx.x >> 5;
    int wm = wid >> 1, wn = wid & 1, g = lane >> 2, q = lane & 3;

    const int wsel[3] = {0, 1, 3};
#pragma unroll 1
    for (int it = 0; it < 3; it++) {
        __syncthreads();
        load_B(g_W[wsel[it]], smem);
        __syncthreads();
        float C[2][8][4];
        zero_C(C);
        mainloop(smem, C);

        if (it < 2) {
            float* dstbuf = (it == 0) ? g_P : g_Q;
#pragma unroll
            for (int mt = 0; mt < 2; mt++)
#pragma unroll
                for (int nt = 0; nt < 8; nt++) {
                    int row = m0 + wm * 32 + mt * 16 + g;
                    int col = wn * 64 + nt * 8 + q * 2;
                    if (row < NN)
                        *reinterpret_cast<float2*>(dstbuf + (size_t)row * FD + col) =
                            make_float2(C[mt][nt][0], C[mt][nt][1]);
                    if (row + 8 < NN)
                        *reinterpret_cast<float2*>(dstbuf + (size_t)(row + 8) * FD + col) =
                            make_float2(C[mt][nt][2], C[mt][nt][3]);
                }
        } else {
            __syncthreads();
            float* Gst = reinterpret_cast<float*>(smem);
            stage_C(C, Gst);
            __syncthreads();
            int half = lane >> 4;
            int r = wid * 16 + (lane & 15);
            int node = m0 + r;
            float acc = 0.f;
            const float4* Gp = reinterpret_cast<const float4*>(Gst + r * 132 + half * 64);
            const float4* Bp = reinterpret_cast<const float4*>(be1 + half * 64);
            const float4* Wp = reinterpret_cast<const float4*>(We2 + half * 64);
#pragma unroll
            for (int j = 0; j < 16; j++) {
                float4 gv = Gp[j], bv = Bp[j], wv = Wp[j];
                acc += fmaxf(gv.x + bv.x, 0.f) * wv.x;
                acc += fmaxf(gv.y + bv.y, 0.f) * wv.y;
                acc += fmaxf(gv.z + bv.z, 0.f) * wv.z;
                acc += fmaxf(gv.w + bv.w, 0.f) * wv.w;
            }
            acc += __shfl_xor_sync(0xffffffffu, acc, 16);
            if (half == 0 && node < NN) g_eps[node] = acc + be2[0];
        }
    }
}

// ---------------- CSR build --------------------------------------------------
__global__ void k_scan() {
    __shared__ int wsum[32];
    int tid = threadIdx.x;
    int lane = tid & 31, w = tid >> 5;
    int carry = 0;
    for (int c = 0; c < (NN + 1024) / 1024; c++) {
        int idx = c * 1024 + tid;
        int v = (idx < NN) ? g_deg[idx] : 0;
        int x = v;
#pragma unroll
        for (int d = 1; d < 32; d <<= 1) {
            int t = __shfl_up_sync(0xffffffffu, x, d);
            if (lane >= d) x += t;
        }
        if (lane == 31) wsum[w] = x;
        __syncthreads();
        if (w == 0) {
            int y = wsum[lane];
#pragma unroll
            for (int d = 1; d < 32; d <<= 1) {
                int t = __shfl_up_sync(0xffffffffu, y, d);
                if (lane >= d) y += t;
            }
            wsum[lane] = y;
        }
        __syncthreads();
        int woff = (w > 0) ? wsum[w - 1] : 0;
        int excl = carry + woff + x - v;
        if (idx <= NN) {
            g_off[idx] = excl;
            if (idx < NN) g_cur[idx] = excl;
        }
        carry += wsum[31];
        __syncthreads();
    }
}

__global__ void k_scatter(const int* __restrict__ dst) {
    int e = blockIdx.x * blockDim.x + threadIdx.x;
    if (e < NE) {
        int p = atomicAdd(&g_cur[dst[e]], 1);
        g_eid[p] = e;
    }
}

// ---------------- fused softmax + aggregation: warp per node ----------------
__global__ void k_agg(const float* __restrict__ nf, const float* __restrict__ gh,
                      const int* __restrict__ src, float* __restrict__ out) {
    int node = (blockIdx.x * blockDim.x + threadIdx.x) >> 5;
    int lane = threadIdx.x & 31;
    if (node >= NN) return;
    int beg = g_off[node], end = g_off[node + 1];

    // pass 1: max + denom (strided over this node's edges)
    float m = -INFINITY;
    for (int i = beg + lane; i < end; i += 32) m = fmaxf(m, g_a[g_eid[i]]);
#pragma unroll
    for (int d = 16; d; d >>= 1) m = fmaxf(m, __shfl_xor_sync(0xffffffffu, m, d));
    float s = 0.f;
    for (int i = beg + lane; i < end; i += 32) s += __expf(g_a[g_eid[i]] - m);
#pragma unroll
    for (int d = 16; d; d >>= 1) s += __shfl_xor_sync(0xffffffffu, s, d);
    float inv = (s > 0.f) ? 1.f / s : 0.f;

    // pass 2: weighted aggregate (lane = feature quad)
    float4 hv = make_float4(0.f, 0.f, 0.f, 0.f);
    const float4* nf4 = reinterpret_cast<const float4*>(nf);
    for (int i = beg; i < end; i++) {
        int e = g_eid[i];
        float w = __expf(g_a[e] - m) * inv;
        int es = src[e];
        float4 gv = *reinterpret_cast<const float4*>(gh + (size_t)e * FD + lane * 4);
        float4 h = nf4[(size_t)es * 32 + lane];
        hv.x += w * gv.x * h.x;
        hv.y += w * gv.y * h.y;
        hv.z += w * gv.z * h.z;
        hv.w += w * gv.w * h.w;
    }
    float ep = 1.f + g_eps[node];
    float4 base = nf4[(size_t)node * 32 + lane];
    float4 r;
    r.x = ep * hv.x + base.x;
    r.y = ep * hv.y + base.y;
    r.z = ep * hv.z + base.z;
    r.w = ep * hv.w + base.w;
    reinterpret_cast<float4*>(out)[(size_t)node * 32 + lane] = r;
}

// ---------------- launch -----------------------------------------------------
extern "C" void kernel_launch(void* const* d_in, const int* in_sizes, int n_in,
                              void* d_out, int out_size) {
    const float* nf = (const float*)d_in[0];
    const float* gh = (const float*)d_in[1];
    const int* src = (const int*)d_in[2];
    const int* dst = (const int*)d_in[3];
    const float* Wa1 = (const float*)d_in[4];
    const float* ba1 = (const float*)d_in[5];
    const float* Wa2 = (const float*)d_in[6];
    const float* ba2 = (const float*)d_in[7];
    const float* We1 = (const float*)d_in[8];
    const float* be1 = (const float*)d_in[9];
    const float* We2 = (const float*)d_in[10];
    const float* be2 = (const float*)d_in[11];
    float* out = (float*)d_out;

    cudaFuncSetAttribute(k_node, cudaFuncAttributeMaxDynamicSharedMemorySize, SMEM_BYTES);
    cudaFuncSetAttribute(k_edge, cudaFuncAttributeMaxDynamicSharedMemorySize, SMEM_BYTES);

    k_prep<<<128, 256>>>(Wa1, We1);
    k_node<<<(NN + TILE - 1) / TILE, 256, SMEM_BYTES>>>(nf, be1, We2, be2);
    k_edge<<<NE / TILE, 256, SMEM_BYTES>>>(gh, src, dst, ba1, Wa2, ba2);
    k_scan<<<1, 1024>>>();
    k_scatter<<<(NE + 255) / 256, 256>>>(dst);
    k_agg<<<(NN * 32 + 255) / 256, 256>>>(nf, gh, src, out);
}

// round 4
// speedup vs baseline: 1.4793x; 1.0441x over previous
#include <cuda_runtime.h>
#include <cuda_fp16.h>
#include <cstdint>
#include <cstddef>

#define FD 128
#define NN 25000
#define NE 400000
#define TILE 128
// smem: A 128x136 fp16 (34816 B) + B 128x136 fp16 (34816 B); staging Gst 128x132 f32 overlaps
#define SMEM_BYTES (2 * 128 * 136 * 2)

// ---------------- device scratch (no allocation allowed) --------------------
__device__ float g_P[NN * FD];
__device__ float g_Q[NN * FD];
__device__ float g_eps[NN];
__device__ float g_a[NE];
__device__ float g_as[NE];   // a in CSR order
__device__ int g_esrc[NE];   // src in CSR order
__device__ __half g_W[4][FD * FD];  // [Wt,Wm,Wb,We1] stored [n*FD+k]
__device__ int g_deg[NN];
__device__ int g_off[NN];
__device__ int g_end[NN];
__device__ int g_cur[NN];
__device__ int g_eid[NE];
__device__ int g_cursor;

// ---------------- helpers ----------------------------------------------------
__device__ __forceinline__ uint32_t smem_u32(const void* p) {
    uint32_t a;
    asm("{ .reg .u64 t; cvta.to.shared.u64 t, %1; cvt.u32.u64 %0, t; }" : "=r"(a) : "l"(p));
    return a;
}
__device__ __forceinline__ void ldsm4(uint32_t r[4], uint32_t addr) {
    asm volatile("ldmatrix.sync.aligned.m8n8.x4.shared.b16 {%0,%1,%2,%3}, [%4];"
                 : "=r"(r[0]), "=r"(r[1]), "=r"(r[2]), "=r"(r[3])
                 : "r"(addr));
}
__device__ __forceinline__ void mma16816(float c[4], const uint32_t a[4], uint32_t b0,
                                         uint32_t b1) {
    asm volatile(
        "mma.sync.aligned.m16n8k16.row.col.f32.f16.f16.f32 "
        "{%0,%1,%2,%3},{%4,%5,%6,%7},{%8,%9},{%0,%1,%2,%3};"
        : "+f"(c[0]), "+f"(c[1]), "+f"(c[2]), "+f"(c[3])
        : "r"(a[0]), "r"(a[1]), "r"(a[2]), "r"(a[3]), "r"(b0), "r"(b1));
}
__device__ __forceinline__ uint32_t pack_h2(float x, float y) {
    __half2 h = __floats2half2_rn(x, y);
    return *reinterpret_cast<uint32_t*>(&h);
}

// ---------------- weight convert + zero histogram ---------------------------
__global__ void k_prep(const float* __restrict__ Wa1, const float* __restrict__ We1) {
    int stride = gridDim.x * blockDim.x;
    int tid = blockIdx.x * blockDim.x + threadIdx.x;
    if (blockIdx.x == 0 && threadIdx.x == 0) g_cursor = 0;
    for (int i = tid; i < 4 * FD * FD; i += stride) {
        int m = i >> 14;
        int r = i & (FD * FD - 1);
        int n = r >> 7;
        int k = r & 127;
        float w = (m < 3) ? Wa1[(m * FD + k) * FD + n] : We1[k * FD + n];
        g_W[m][n * FD + k] = __float2half(w);
    }
    for (int i = tid; i < NN; i += stride) g_deg[i] = 0;
}

// ---------------- GEMM building blocks (256 threads, C tile 128x128) --------
__device__ __forceinline__ void load_A(const float* __restrict__ src, int row0, int maxrow,
                                       char* smem) {
    int t = threadIdx.x;
#pragma unroll
    for (int it = 0; it < 16; it++) {
        int linear = it * 256 + t;
        int r = linear >> 5;
        int c = (linear & 31) * 4;
        float4 v = make_float4(0.f, 0.f, 0.f, 0.f);
        if (row0 + r < maxrow)
            v = *reinterpret_cast<const float4*>(src + (size_t)(row0 + r) * FD + c);
        uint2 pk;
        pk.x = pack_h2(v.x, v.y);
        pk.y = pack_h2(v.z, v.w);
        *reinterpret_cast<uint2*>(smem + r * 272 + c * 2) = pk;
    }
}
__device__ __forceinline__ void load_B(const __half* __restrict__ w, char* smem) {
    const uint32_t* s4 = reinterpret_cast<const uint32_t*>(w);
    int t = threadIdx.x;
    char* sB = smem + 34816;
#pragma unroll
    for (int it = 0; it < 32; it++) {
        int linear = it * 256 + t;
        int n = linear >> 6;
        int kk = linear & 63;
        *reinterpret_cast<uint32_t*>(sB + n * 272 + kk * 4) = s4[linear];
    }
}

// warp grid 4(M) x 2(N); warp tile 32x64; per-thread C[2][8][4]
__device__ __forceinline__ void mainloop(char* smem, float C[2][8][4]) {
    int lane = threadIdx.x & 31;
    int wid = threadIdx.x >> 5;
    int wm = wid >> 1, wn = wid & 1;
    uint32_t sA = smem_u32(smem);
    uint32_t sB = sA + 34816;
    uint32_t aA0 = sA + (wm * 32 + (lane & 15)) * 272 + (lane >> 4) * 16;
    uint32_t aA1 = aA0 + 16 * 272;
    uint32_t aB[4];
#pragma unroll
    for (int p = 0; p < 4; p++)
        aB[p] = sB + (wn * 64 + p * 16 + (lane & 7) + ((lane >> 4) & 1) * 8) * 272 +
                ((lane >> 3) & 1) * 16;
#pragma unroll
    for (int ks = 0; ks < 8; ks++) {
        uint32_t A0[4], A1[4], Bf[4][4];
        ldsm4(A0, aA0 + ks * 32);
        ldsm4(A1, aA1 + ks * 32);
#pragma unroll
        for (int p = 0; p < 4; p++) ldsm4(Bf[p], aB[p] + ks * 32);
#pragma unroll
        for (int p = 0; p < 4; p++) {
            mma16816(C[0][2 * p], A0, Bf[p][0], Bf[p][1]);
            mma16816(C[1][2 * p], A1, Bf[p][0], Bf[p][1]);
            mma16816(C[0][2 * p + 1], A0, Bf[p][2], Bf[p][3]);
            mma16816(C[1][2 * p + 1], A1, Bf[p][2], Bf[p][3]);
        }
    }
}

__device__ __forceinline__ void zero_C(float C[2][8][4]) {
#pragma unroll
    for (int a = 0; a < 2; a++)
#pragma unroll
        for (int b = 0; b < 8; b++)
#pragma unroll
            for (int c = 0; c < 4; c++) C[a][b][c] = 0.f;
}

__device__ __forceinline__ void stage_C(float C[2][8][4], float* Gst) {
    int lane = threadIdx.x & 31;
    int wid = threadIdx.x >> 5;
    int wm = wid >> 1, wn = wid & 1, g = lane >> 2, q = lane & 3;
#pragma unroll
    for (int mt = 0; mt < 2; mt++)
#pragma unroll
        for (int nt = 0; nt < 8; nt++) {
            int row = wm * 32 + mt * 16 + g;
            int col = wn * 64 + nt * 8 + q * 2;
            *reinterpret_cast<float2*>(Gst + row * 132 + col) = make_float2(C[mt][nt][0], C[mt][nt][1]);
            *reinterpret_cast<float2*>(Gst + (row + 8) * 132 + col) = make_float2(C[mt][nt][2], C[mt][nt][3]);
        }
}

// ---------------- edge kernel: a[e] = relu(G+P[src]+Q[dst]+ba1).Wa2 + ba2 ---
__global__ void __launch_bounds__(256, 2)
k_edge(const float* __restrict__ gh, const int* __restrict__ src, const int* __restrict__ dst,
       const float* __restrict__ ba1, const float* __restrict__ Wa2, const float* __restrict__ ba2) {
    extern __shared__ char smem[];
    int m0 = blockIdx.x * TILE;
    int lane = threadIdx.x & 31;
    int wid = threadIdx.x >> 5;
    int half = lane >> 4;
    int r = wid * 16 + (lane & 15);
    int e = m0 + r;
    int es = src[e], ed = dst[e];
    if (half == 0) atomicAdd(&g_deg[ed], 1);  // overlaps with tile load + mainloop

    load_A(gh, m0, NE, smem);
    load_B(g_W[2], smem);
    __syncthreads();

    float C[2][8][4];
    zero_C(C);
    mainloop(smem, C);
    __syncthreads();
    float* Gst = reinterpret_cast<float*>(smem);
    stage_C(C, Gst);
    __syncthreads();

    float acc = 0.f;
    const float4* Gp = reinterpret_cast<const float4*>(Gst + r * 132 + half * 64);
    const float4* Pp = reinterpret_cast<const float4*>(g_P + (size_t)es * FD + half * 64);
    const float4* Qp = reinterpret_cast<const float4*>(g_Q + (size_t)ed * FD + half * 64);
    const float4* Bp = reinterpret_cast<const float4*>(ba1 + half * 64);
    const float4* Wp = reinterpret_cast<const float4*>(Wa2 + half * 64);
#pragma unroll
    for (int j = 0; j < 16; j++) {
        float4 gv = Gp[j], pv = Pp[j], qv = Qp[j], bv = Bp[j], wv = Wp[j];
        acc += fmaxf(gv.x + pv.x + qv.x + bv.x, 0.f) * wv.x;
        acc += fmaxf(gv.y + pv.y + qv.y + bv.y, 0.f) * wv.y;
        acc += fmaxf(gv.z + pv.z + qv.z + bv.z, 0.f) * wv.z;
        acc += fmaxf(gv.w + pv.w + qv.w + bv.w, 0.f) * wv.w;
    }
    acc += __shfl_xor_sync(0xffffffffu, acc, 16);
    if (half == 0) g_a[e] = acc + ba2[0];
}

// ---------------- node kernel: P = nf@Wt, Q = nf@Wm, eps --------------------
__global__ void __launch_bounds__(256, 2)
k_node(const float* __restrict__ nf, const float* __restrict__ be1, const float* __restrict__ We2,
       const float* __restrict__ be2) {
    extern __shared__ char smem[];
    int m0 = blockIdx.x * TILE;
    load_A(nf, m0, NN, smem);

    int lane = threadIdx.x & 31;
    int wid = threadIdx.x >> 5;
    int wm = wid >> 1, wn = wid & 1, g = lane >> 2, q = lane & 3;

    const int wsel[3] = {0, 1, 3};
#pragma unroll 1
    for (int it = 0; it < 3; it++) {
        __syncthreads();
        load_B(g_W[wsel[it]], smem);
        __syncthreads();
        float C[2][8][4];
        zero_C(C);
        mainloop(smem, C);

        if (it < 2) {
            float* dstbuf = (it == 0) ? g_P : g_Q;
#pragma unroll
            for (int mt = 0; mt < 2; mt++)
#pragma unroll
                for (int nt = 0; nt < 8; nt++) {
                    int row = m0 + wm * 32 + mt * 16 + g;
                    int col = wn * 64 + nt * 8 + q * 2;
                    if (row < NN)
                        *reinterpret_cast<float2*>(dstbuf + (size_t)row * FD + col) =
                            make_float2(C[mt][nt][0], C[mt][nt][1]);
                    if (row + 8 < NN)
                        *reinterpret_cast<float2*>(dstbuf + (size_t)(row + 8) * FD + col) =
                            make_float2(C[mt][nt][2], C[mt][nt][3]);
                }
        } else {
            __syncthreads();
            float* Gst = reinterpret_cast<float*>(smem);
            stage_C(C, Gst);
            __syncthreads();
            int half = lane >> 4;
            int r = wid * 16 + (lane & 15);
            int node = m0 + r;
            float acc = 0.f;
            const float4* Gp = reinterpret_cast<const float4*>(Gst + r * 132 + half * 64);
            const float4* Bp = reinterpret_cast<const float4*>(be1 + half * 64);
            const float4* Wp = reinterpret_cast<const float4*>(We2 + half * 64);
#pragma unroll
            for (int j = 0; j < 16; j++) {
                float4 gv = Gp[j], bv = Bp[j], wv = Wp[j];
                acc += fmaxf(gv.x + bv.x, 0.f) * wv.x;
                acc += fmaxf(gv.y + bv.y, 0.f) * wv.y;
                acc += fmaxf(gv.z + bv.z, 0.f) * wv.z;
                acc += fmaxf(gv.w + bv.w, 0.f) * wv.w;
            }
            acc += __shfl_xor_sync(0xffffffffu, acc, 16);
            if (half == 0 && node < NN) g_eps[node] = acc + be2[0];
        }
    }
}

// ---------------- one-shot parallel range assignment (order-free CSR) -------
// Segment ORDER is irrelevant for correctness: each node just needs a disjoint
// contiguous range. Block-local scan + one atomicAdd on a global cursor.
__global__ void k_scan_fast() {
    __shared__ int wsum[8];
    __shared__ int sbase;
    int n = blockIdx.x * 256 + threadIdx.x;
    int lane = threadIdx.x & 31, w = threadIdx.x >> 5;
    int v = (n < NN) ? g_deg[n] : 0;
    int x = v;
#pragma unroll
    for (int d = 1; d < 32; d <<= 1) {
        int t = __shfl_up_sync(0xffffffffu, x, d);
        if (lane >= d) x += t;
    }
    if (lane == 31) wsum[w] = x;
    __syncthreads();
    if (threadIdx.x == 0) {
        int run = 0;
#pragma unroll
        for (int i = 0; i < 8; i++) {
            int t = wsum[i];
            wsum[i] = run;
            run += t;
        }
        sbase = atomicAdd(&g_cursor, run);
    }
    __syncthreads();
    int off = sbase + wsum[w] + x - v;  // exclusive within block + global base
    if (n < NN) {
        g_off[n] = off;
        g_cur[n] = off;
        g_end[n] = off + v;
    }
}

// ---------------- scatter: build CSR-ordered a/src alongside eid ------------
__global__ void k_scatter(const int* __restrict__ dst, const int* __restrict__ src) {
    int e = blockIdx.x * blockDim.x + threadIdx.x;
    if (e < NE) {
        int p = atomicAdd(&g_cur[dst[e]], 1);
        g_eid[p] = e;
        g_esrc[p] = src[e];
        g_as[p] = g_a[e];
    }
}

// ---------------- fused softmax + aggregation: warp per node ----------------
__global__ void k_agg(const float* __restrict__ nf, const float* __restrict__ gh,
                      float* __restrict__ out) {
    int node = (blockIdx.x * blockDim.x + threadIdx.x) >> 5;
    int lane = threadIdx.x & 31;
    if (node >= NN) return;
    int beg = g_off[node], end = g_end[node];

    // pass 1: max + denom over contiguous g_as segment
    float m = -INFINITY;
    for (int i = beg + lane; i < end; i += 32) m = fmaxf(m, g_as[i]);
#pragma unroll
    for (int d = 16; d; d >>= 1) m = fmaxf(m, __shfl_xor_sync(0xffffffffu, m, d));
    float s = 0.f;
    for (int i = beg + lane; i < end; i += 32) s += __expf(g_as[i] - m);
#pragma unroll
    for (int d = 16; d; d >>= 1) s += __shfl_xor_sync(0xffffffffu, s, d);
    float inv = (s > 0.f) ? 1.f / s : 0.f;

    // pass 2: weighted aggregate (lane = feature quad); a/src sequential, gh random
    float4 hv = make_float4(0.f, 0.f, 0.f, 0.f);
    const float4* nf4 = reinterpret_cast<const float4*>(nf);
#pragma unroll 2
    for (int i = beg; i < end; i++) {
        float w = __expf(g_as[i] - m) * inv;
        int e = g_eid[i];
        int es = g_esrc[i];
        float4 gv = *reinterpret_cast<const float4*>(gh + (size_t)e * FD + lane * 4);
        float4 h = nf4[(size_t)es * 32 + lane];
        hv.x += w * gv.x * h.x;
        hv.y += w * gv.y * h.y;
        hv.z += w * gv.z * h.z;
        hv.w += w * gv.w * h.w;
    }
    float ep = 1.f + g_eps[node];
    float4 base = nf4[(size_t)node * 32 + lane];
    float4 r;
    r.x = ep * hv.x + base.x;
    r.y = ep * hv.y + base.y;
    r.z = ep * hv.z + base.z;
    r.w = ep * hv.w + base.w;
    reinterpret_cast<float4*>(out)[(size_t)node * 32 + lane] = r;
}

// ---------------- launch -----------------------------------------------------
extern "C" void kernel_launch(void* const* d_in, const int* in_sizes, int n_in,
                              void* d_out, int out_size) {
    const float* nf = (const float*)d_in[0];
    const float* gh = (const float*)d_in[1];
    const int* src = (const int*)d_in[2];
    const int* dst = (const int*)d_in[3];
    const float* Wa1 = (const float*)d_in[4];
    const float* ba1 = (const float*)d_in[5];
    const float* Wa2 = (const float*)d_in[6];
    const float* ba2 = (const float*)d_in[7];
    const float* We1 = (const float*)d_in[8];
    const float* be1 = (const float*)d_in[9];
    const float* We2 = (const float*)d_in[10];
    const float* be2 = (const float*)d_in[11];
    float* out = (float*)d_out;

    cudaFuncSetAttribute(k_node, cudaFuncAttributeMaxDynamicSharedMemorySize, SMEM_BYTES);
    cudaFuncSetAttribute(k_edge, cudaFuncAttributeMaxDynamicSharedMemorySize, SMEM_BYTES);

    k_prep<<<128, 256>>>(Wa1, We1);
    k_node<<<(NN + TILE - 1) / TILE, 256, SMEM_BYTES>>>(nf, be1, We2, be2);
    k_edge<<<NE / TILE, 256, SMEM_BYTES>>>(gh, src, dst, ba1, Wa2, ba2);
    k_scan_fast<<<(NN + 255) / 256, 256>>>();
    k_scatter<<<(NE + 255) / 256, 256>>>(dst, src);
    k_agg<<<(NN * 32 + 255) / 256, 256>>>(nf, gh, out);
}